// round 1
// baseline (speedup 1.0000x reference)
#include <cuda_runtime.h>
#include <cstdint>

#define Nn 32
#define Cc 64
#define Hh 112
#define Wd 112
#define HW (Hh*Wd)            // 12544
#define NHW (Nn*HW)           // 401408
#define TOT (Nn*Cc*HW)        // 25690112
#define BN_EPS 1e-5

// ---------------- scratch (device globals; no allocation at runtime) ----------
__device__ unsigned long long g_xbits[NHW];        // 3.2 MB packed input signs
__device__ unsigned long long g_wbits[Cc*9];       // packed weight signs
__device__ int                g_wdelta[Cc*9];      // 64 - 2*popc(wbits) per (co,tap)
__device__ float              g_alpha[Cc];
__device__ long long          g_sum[Cc];
__device__ long long          g_ss[Cc];
__device__ short              g_conv[TOT];         // 51.4 MB int16 conv result
__device__ float              g_A[Cc], g_B[Cc];

// ---------------- K0: pack W, alpha, zero stats --------------------------------
__global__ void packW_k(const float* __restrict__ W) {
    int c = threadIdx.x;          // one thread per output channel (64 threads)
    if (c >= Cc) return;
    g_sum[c] = 0; g_ss[c] = 0;
    float asum = 0.f;
    #pragma unroll
    for (int t = 0; t < 9; t++) {
        unsigned long long bits = 0;
        for (int ci = 0; ci < Cc; ci++) {
            float w = W[(size_t)(c*Cc + ci)*9 + t];
            asum += fabsf(w);
            bits |= ((unsigned long long)(__float_as_uint(w) >> 31)) << ci;
        }
        g_wbits[c*9 + t]  = bits;
        g_wdelta[c*9 + t] = 64 - 2*__popcll(bits);
    }
    g_alpha[c] = asum / 576.f;
}

// ---------------- K1: pack x signs ---------------------------------------------
__global__ void packX_k(const float* __restrict__ x) {
    int idx = blockIdx.x*blockDim.x + threadIdx.x;
    if (idx >= NHW) return;
    int n = idx / HW;
    int p = idx - n*HW;
    const float* base = x + (size_t)n*Cc*HW + p;
    unsigned lo = 0, hi = 0;
    #pragma unroll
    for (int c = 0; c < 32; c++)
        lo |= (__float_as_uint(base[(size_t)c*HW]) >> 31) << c;
    #pragma unroll
    for (int c = 0; c < 32; c++)
        hi |= (__float_as_uint(base[(size_t)(c+32)*HW]) >> 31) << c;
    g_xbits[idx] = ((unsigned long long)hi << 32) | lo;
}

// ---------------- K2: popcount conv --------------------------------------------
// 16x16 output tile per block (112 = 7*16, no ragged tiles), halo 18x18.
__global__ __launch_bounds__(256) void conv_k() {
    __shared__ unsigned long long xs[18*18];
    __shared__ unsigned long long wb[Cc*9];
    __shared__ int                wd[Cc*9];

    int n  = blockIdx.z;
    int h0 = blockIdx.y * 16, w0 = blockIdx.x * 16;
    int tx = threadIdx.x, ty = threadIdx.y;
    int tid = ty*16 + tx;

    // load halo'd x-bits tile (zero-fill outside image)
    for (int j = tid; j < 18*18; j += 256) {
        int lh = j / 18, lw = j - lh*18;
        int gh = h0 + lh - 1, gw = w0 + lw - 1;
        unsigned long long v = 0ull;
        if (gh >= 0 && gh < Hh && gw >= 0 && gw < Wd)
            v = g_xbits[(size_t)n*HW + gh*Wd + gw];
        xs[j] = v;
    }
    // stage weight bits + padding corrections
    for (int j = tid; j < Cc*9; j += 256) { wb[j] = g_wbits[j]; wd[j] = g_wdelta[j]; }
    __syncthreads();

    int oh = h0 + ty, ow = w0 + tx;

    unsigned long long xv[9];
    #pragma unroll
    for (int kh = 0; kh < 3; kh++)
        #pragma unroll
        for (int kw = 0; kw < 3; kw++)
            xv[kh*3+kw] = xs[(ty+kh)*18 + (tx+kw)];

    // taps that fall outside the image (zero-padded region)
    unsigned invm = 0;
    #pragma unroll
    for (int kh = 0; kh < 3; kh++)
        #pragma unroll
        for (int kw = 0; kw < 3; kw++) {
            int hh = oh + kh - 1, ww = ow + kw - 1;
            if (hh < 0 || hh >= Hh || ww < 0 || ww >= Wd) invm |= 1u << (kh*3+kw);
        }

    size_t obase = ((size_t)n*Cc)*HW + (size_t)oh*Wd + ow;

    #pragma unroll 4
    for (int co = 0; co < Cc; co++) {
        int pc = 0;
        #pragma unroll
        for (int t = 0; t < 9; t++)
            pc += __popcll(xv[t] ^ wb[co*9 + t]);
        int s = 576 - 2*pc;
        if (invm) {  // subtract phantom contributions of zero-padded taps
            unsigned m = invm;
            while (m) { int t = __ffs(m) - 1; m &= m - 1; s -= wd[co*9 + t]; }
        }
        g_conv[obase + (size_t)co*HW] = (short)s;
    }
}

// ---------------- K2b: exact integer per-channel stats -------------------------
__global__ __launch_bounds__(256) void reduce_k() {
    int n = blockIdx.x, c = blockIdx.y;
    const short* p = g_conv + ((size_t)n*Cc + c)*HW;
    int s = 0, ssi = 0;  // per-thread: |s|<=576*49, ss<=331776*49 -> fits int32
    for (int i = threadIdx.x; i < HW; i += 256) {
        int v = p[i];
        s += v; ssi += v*v;
    }
    // warp reduce (warp ss <= 32*16.3M < 2^31, safe)
    #pragma unroll
    for (int o = 16; o; o >>= 1) {
        s   += __shfl_xor_sync(0xffffffffu, s,   o);
        ssi += __shfl_xor_sync(0xffffffffu, ssi, o);
    }
    __shared__ long long sh_s[8], sh_ss[8];
    int wid = threadIdx.x >> 5, lid = threadIdx.x & 31;
    if (lid == 0) { sh_s[wid] = s; sh_ss[wid] = ssi; }
    __syncthreads();
    if (threadIdx.x == 0) {
        long long bs = 0, bss = 0;
        #pragma unroll
        for (int w = 0; w < 8; w++) { bs += sh_s[w]; bss += sh_ss[w]; }
        atomicAdd((unsigned long long*)&g_sum[c], (unsigned long long)bs);
        atomicAdd((unsigned long long*)&g_ss[c],  (unsigned long long)bss);
    }
}

// ---------------- K3: fold alpha + BN + gamma/beta into per-channel affine -----
__global__ void stats_k(const float* __restrict__ gamma, const float* __restrict__ beta) {
    int c = threadIdx.x;
    if (c >= Cc) return;
    double mean = (double)g_sum[c] / (double)NHW;
    double ex2  = (double)g_ss[c]  / (double)NHW;
    double a    = (double)g_alpha[c];
    double var  = a*a*(ex2 - mean*mean);
    double rs   = 1.0 / sqrt(var + BN_EPS);
    double g    = (double)gamma[c];
    g_A[c] = (float)(a * rs * g);
    g_B[c] = (float)((double)beta[c] - a * mean * rs * g);
}

// ---------------- K4: affine + hardtanh + residual, float4 ---------------------
__global__ __launch_bounds__(256) void apply_k(const float* __restrict__ x,
                                               float* __restrict__ out) {
    size_t i = (size_t)blockIdx.x*blockDim.x + threadIdx.x;   // group-of-4 index
    size_t base = i * 4;
    if (base >= TOT) return;
    int c = (int)((base / HW) % Cc);     // HW % 4 == 0 -> whole group same channel
    float A = g_A[c], B = g_B[c];
    short4 sv = ((const short4*)g_conv)[i];
    float4 xr = ((const float4*)x)[i];
    float4 o;
    o.x = fminf(fmaxf(fmaf((float)sv.x, A, B), -1.f), 1.f) + xr.x;
    o.y = fminf(fmaxf(fmaf((float)sv.y, A, B), -1.f), 1.f) + xr.y;
    o.z = fminf(fmaxf(fmaf((float)sv.z, A, B), -1.f), 1.f) + xr.z;
    o.w = fminf(fmaxf(fmaf((float)sv.w, A, B), -1.f), 1.f) + xr.w;
    ((float4*)out)[i] = o;
}

// ---------------- launcher ------------------------------------------------------
extern "C" void kernel_launch(void* const* d_in, const int* in_sizes, int n_in,
                              void* d_out, int out_size) {
    const float* x     = (const float*)d_in[0];
    const float* W     = (const float*)d_in[1];
    const float* gamma = (const float*)d_in[2];
    const float* beta  = (const float*)d_in[3];
    float* out = (float*)d_out;

    packW_k<<<1, 64>>>(W);
    packX_k<<<(NHW + 255)/256, 256>>>(x);
    conv_k<<<dim3(7, 7, Nn), dim3(16, 16)>>>();
    reduce_k<<<dim3(Nn, Cc), 256>>>();
    stats_k<<<1, 64>>>(gamma, beta);
    apply_k<<<(TOT/4 + 255)/256, 256>>>(x, out);
}

// round 3
// speedup vs baseline: 1.1768x; 1.1768x over previous
#include <cuda_runtime.h>
#include <cstdint>

#define Nn 32
#define Cc 64
#define Hh 112
#define Wd 112
#define HW (Hh*Wd)            // 12544
#define NHW (Nn*HW)           // 401408
#define TOT (Nn*Cc*HW)        // 25690112
#define BN_EPS 1e-5

// ---------------- scratch (device globals) -------------------------------------
__device__ unsigned long long g_xbits[NHW];        // packed input signs (3.2 MB)
__device__ unsigned long long g_wbits[Cc*9];       // packed weight signs
__device__ float              g_alpha[Cc];
__device__ long long          g_sum[Cc];
__device__ long long          g_ss[Cc];
__device__ short              g_conv[TOT];         // NHWC [n][p][c] int16 conv result
__device__ float              g_A[Cc], g_B[Cc];

// ---------------- K0: pack W (parallel) + alpha + zero stats -------------------
// 1 block, 576 threads: thread = (co, tap)
__global__ void packW_k(const float* __restrict__ W) {
    __shared__ float asum[Cc][9];
    int tid = threadIdx.x;          // 0..575
    int co = tid / 9, tap = tid - co*9;
    unsigned long long bits = 0ull;
    float a = 0.f;
    for (int ci = 0; ci < Cc; ci++) {
        float w = W[(size_t)(co*Cc + ci)*9 + tap];
        a += fabsf(w);
        bits |= ((unsigned long long)(__float_as_uint(w) >> 31)) << ci;
    }
    g_wbits[co*9 + tap] = bits;
    asum[co][tap] = a;
    if (tap == 0) { g_sum[co] = 0; g_ss[co] = 0; }
    __syncthreads();
    if (tap == 0) {
        float t = 0.f;
        #pragma unroll
        for (int k = 0; k < 9; k++) t += asum[co][k];
        g_alpha[co] = t / 576.f;
    }
}

// ---------------- K1: pack x signs ---------------------------------------------
__global__ __launch_bounds__(256) void packX_k(const float* __restrict__ x) {
    int idx = blockIdx.x*blockDim.x + threadIdx.x;
    if (idx >= NHW) return;
    int n = idx / HW;
    int p = idx - n*HW;
    const float* base = x + (size_t)n*Cc*HW + p;
    unsigned lo = 0, hi = 0;
    #pragma unroll
    for (int c = 0; c < 32; c++)
        lo |= (__float_as_uint(base[(size_t)c*HW]) >> 31) << c;
    #pragma unroll
    for (int c = 0; c < 32; c++)
        hi |= (__float_as_uint(base[(size_t)(c+32)*HW]) >> 31) << c;
    g_xbits[idx] = ((unsigned long long)hi << 32) | lo;
}

// ---------------- K2: popcount conv + fused exact BN statistics ----------------
// 16x16 pixel tile per block. 256 threads = 32 channel-pairs x 8 pixel-groups.
// Weights live in registers; x-bits broadcast from smem; NHWC coalesced stores.
__global__ __launch_bounds__(256, 2) void conv_k() {
    __shared__ unsigned long long xs[18*18];
    __shared__ int st[4][8][32];                    // s0, ss0, s1, ss1 per (group,pair)

    int tid  = threadIdx.x;
    int pair = tid & 31;            // channel pair: c0 = 2*pair, c1 = c0+1
    int grp  = tid >> 5;            // warp == pixel group
    int n  = blockIdx.z;
    int h0 = blockIdx.y * 16, w0 = blockIdx.x * 16;

    // load halo'd x-bits tile (zero-fill outside image)
    for (int j = tid; j < 18*18; j += 256) {
        int lh = j / 18, lw = j - lh*18;
        int gh = h0 + lh - 1, gw = w0 + lw - 1;
        unsigned long long v = 0ull;
        if (gh >= 0 && gh < Hh && gw >= 0 && gw < Wd)
            v = g_xbits[(size_t)n*HW + gh*Wd + gw];
        xs[j] = v;
    }

    int c0 = pair*2;
    unsigned long long wb0[9], wb1[9];
    #pragma unroll
    for (int t = 0; t < 9; t++) {
        wb0[t] = g_wbits[c0*9 + t];
        wb1[t] = g_wbits[(c0+1)*9 + t];
    }
    __syncthreads();

    const bool border = (h0 == 0) | (w0 == 0) | (h0 == Hh-16) | (w0 == Wd-16);
    int as0 = 0, ass0 = 0, as1 = 0, ass1 = 0;

    #pragma unroll 2
    for (int i = 0; i < 32; i++) {
        int lp  = grp*32 + i;                 // local pixel 0..255
        int ohl = lp >> 4, owl = lp & 15;

        unsigned long long xv[9];
        #pragma unroll
        for (int kh = 0; kh < 3; kh++)
            #pragma unroll
            for (int kw = 0; kw < 3; kw++)
                xv[kh*3+kw] = xs[(ohl+kh)*18 + owl + kw];   // warp-broadcast

        int pc0 = 0, pc1 = 0;
        #pragma unroll
        for (int t = 0; t < 9; t++) {
            pc0 += __popcll(xv[t] ^ wb0[t]);
            pc1 += __popcll(xv[t] ^ wb1[t]);
        }
        int s0 = 576 - 2*pc0, s1 = 576 - 2*pc1;

        if (border) {   // subtract phantom taps from the zero-padded halo
            int oh = h0 + ohl, ow = w0 + owl;
            unsigned invm = 0;
            #pragma unroll
            for (int kh = 0; kh < 3; kh++)
                #pragma unroll
                for (int kw = 0; kw < 3; kw++) {
                    int hh = oh + kh - 1, ww = ow + kw - 1;
                    if (hh < 0 || hh >= Hh || ww < 0 || ww >= Wd)
                        invm |= 1u << (kh*3 + kw);
                }
            while (invm) {
                int t = __ffs(invm) - 1; invm &= invm - 1;
                s0 -= 64 - 2*__popcll(wb0[t]);
                s1 -= 64 - 2*__popcll(wb1[t]);
            }
        }

        as0 += s0; ass0 += s0*s0;
        as1 += s1; ass1 += s1*s1;

        int p = (h0 + ohl)*Wd + (w0 + owl);
        unsigned pk = ((unsigned)s0 & 0xFFFFu) | ((unsigned)s1 << 16);
        ((unsigned*)g_conv)[((size_t)n*HW + p)*32 + pair] = pk;   // NHWC, coalesced
    }

    st[0][grp][pair] = as0; st[1][grp][pair] = ass0;
    st[2][grp][pair] = as1; st[3][grp][pair] = ass1;
    __syncthreads();
    if (grp == 0) {
        int bs0=0, bss0=0, bs1=0, bss1=0;
        #pragma unroll
        for (int g = 0; g < 8; g++) {
            bs0 += st[0][g][pair]; bss0 += st[1][g][pair];
            bs1 += st[2][g][pair]; bss1 += st[3][g][pair];
        }
        atomicAdd((unsigned long long*)&g_sum[c0],   (unsigned long long)(long long)bs0);
        atomicAdd((unsigned long long*)&g_ss[c0],    (unsigned long long)(long long)bss0);
        atomicAdd((unsigned long long*)&g_sum[c0+1], (unsigned long long)(long long)bs1);
        atomicAdd((unsigned long long*)&g_ss[c0+1],  (unsigned long long)(long long)bss1);
    }
}

// ---------------- K3: fold alpha + BN + gamma/beta into per-channel affine -----
__global__ void stats_k(const float* __restrict__ gamma, const float* __restrict__ beta) {
    int c = threadIdx.x;
    if (c >= Cc) return;
    double mean = (double)g_sum[c] / (double)NHW;
    double ex2  = (double)g_ss[c]  / (double)NHW;
    double a    = (double)g_alpha[c];
    double var  = a*a*(ex2 - mean*mean);
    double rs   = 1.0 / sqrt(var + BN_EPS);
    double g    = (double)gamma[c];
    g_A[c] = (float)(a * rs * g);
    g_B[c] = (float)((double)beta[c] - a * mean * rs * g);
}

// ---------------- K4: affine + hardtanh + residual (NHWC conv, NCHW x/out) -----
__global__ __launch_bounds__(256) void apply_k(const float* __restrict__ x,
                                               float* __restrict__ out) {
    __shared__ float sA[Cc], sB[Cc];
    int tid = threadIdx.x;
    if (tid < Cc) { sA[tid] = g_A[tid]; sB[tid] = g_B[tid]; }
    __syncthreads();

    size_t P = (size_t)blockIdx.x*256 + tid;      // global pixel id [0, NHW)
    int n = (int)(P / HW);
    int p = (int)(P - (size_t)n*HW);
    const uint4*  cb = (const uint4*)g_conv + P*8;          // 128B of NHWC shorts
    const float*  xb = x   + (size_t)n*Cc*HW + p;
    float*        ob = out + (size_t)n*Cc*HW + p;

    #pragma unroll
    for (int q = 0; q < 8; q++) {
        uint4 v = cb[q];
        #pragma unroll
        for (int w = 0; w < 4; w++) {
            uint32_t u = (&v.x)[w];
            int cA = (q*4 + w)*2;
            int sv0 = (int)((int32_t)(u << 16) >> 16);
            int sv1 = (int)((int32_t)u >> 16);
            float r0 = fminf(fmaxf(fmaf((float)sv0, sA[cA],   sB[cA]),   -1.f), 1.f);
            float r1 = fminf(fmaxf(fmaf((float)sv1, sA[cA+1], sB[cA+1]), -1.f), 1.f);
            ob[(size_t)cA*HW]     = r0 + xb[(size_t)cA*HW];
            ob[(size_t)(cA+1)*HW] = r1 + xb[(size_t)(cA+1)*HW];
        }
    }
}

// ---------------- launcher ------------------------------------------------------
extern "C" void kernel_launch(void* const* d_in, const int* in_sizes, int n_in,
                              void* d_out, int out_size) {
    const float* x     = (const float*)d_in[0];
    const float* W     = (const float*)d_in[1];
    const float* gamma = (const float*)d_in[2];
    const float* beta  = (const float*)d_in[3];
    float* out = (float*)d_out;

    packW_k<<<1, 576>>>(W);
    packX_k<<<(NHW + 255)/256, 256>>>(x);
    conv_k<<<dim3(7, 7, Nn), 256>>>();
    stats_k<<<1, 64>>>(gamma, beta);
    apply_k<<<NHW/256, 256>>>(x, out);
}

// round 4
// speedup vs baseline: 1.2246x; 1.0406x over previous
#include <cuda_runtime.h>
#include <cstdint>

#define Nn 32
#define Cc 64
#define Hh 112
#define Wd 112
#define HW (Hh*Wd)            // 12544
#define NHW (Nn*HW)           // 401408  (= 1568 * 256 exactly)
#define TOT (Nn*Cc*HW)        // 25690112
#define BN_EPS 1e-5
#define PACKX_BLOCKS (NHW/256)  // 1568

typedef unsigned long long u64;

// ---------------- scratch (device globals) -------------------------------------
__device__ u64       g_xbits[NHW];      // packed input signs (3.2 MB)
__device__ u64       g_wbits[Cc*9];     // packed weight signs
__device__ int       g_rowc[3][Cc];     // row-edge corr: [none,N,S]
__device__ int       g_colw[3][Cc];     // west-col corr given row pattern
__device__ int       g_cole[3][Cc];     // east-col corr given row pattern
__device__ float     g_alpha[Cc];
__device__ long long g_sum[Cc];
__device__ long long g_ss[Cc];
__device__ short     g_conv[TOT];       // NHWC [n][p][c] int16 conv result

// ---------------- K0: pack x signs (blocks 0..1567) + pack W (block 1568) ------
__global__ __launch_bounds__(256) void pack_k(const float* __restrict__ x,
                                              const float* __restrict__ W) {
    int tid = threadIdx.x;
    if (blockIdx.x < PACKX_BLOCKS) {
        int idx = blockIdx.x*256 + tid;
        int n = idx / HW;
        int p = idx - n*HW;
        const float* base = x + (size_t)n*Cc*HW + p;
        unsigned lo = 0, hi = 0;
        #pragma unroll
        for (int c = 0; c < 32; c++)
            lo |= (__float_as_uint(base[(size_t)c*HW]) >> 31) << c;
        #pragma unroll
        for (int c = 0; c < 32; c++)
            hi |= (__float_as_uint(base[(size_t)(c+32)*HW]) >> 31) << c;
        g_xbits[idx] = ((u64)hi << 32) | lo;
        return;
    }
    // ---- weight packing block ----
    __shared__ float asum[576];
    __shared__ int   wd_s[Cc][9];
    for (int i = tid; i < 576; i += 256) {
        int co = i / 9, tap = i - co*9;
        u64 bits = 0ull;
        float a = 0.f;
        for (int ci = 0; ci < Cc; ci++) {
            float w = W[(size_t)(co*Cc + ci)*9 + tap];
            a += fabsf(w);
            bits |= ((u64)(__float_as_uint(w) >> 31)) << ci;
        }
        g_wbits[i]    = bits;
        wd_s[co][tap] = 64 - 2*__popcll(bits);
        asum[i]       = a;
    }
    if (tid < Cc) { g_sum[tid] = 0; g_ss[tid] = 0; }
    __syncthreads();
    if (tid < Cc) {
        int co = tid;
        float t = 0.f;
        #pragma unroll
        for (int k = 0; k < 9; k++) t += asum[co*9 + k];
        g_alpha[co] = t / 576.f;
        int w0=wd_s[co][0], w1=wd_s[co][1], w2=wd_s[co][2];
        int w3=wd_s[co][3],               w5=wd_s[co][5];
        int w6=wd_s[co][6], w7=wd_s[co][7], w8=wd_s[co][8];
        g_rowc[0][co] = 0;
        g_rowc[1][co] = w0 + w1 + w2;       // top row of image: taps 0,1,2 invalid
        g_rowc[2][co] = w6 + w7 + w8;       // bottom row: taps 6,7,8 invalid
        g_colw[0][co] = w0 + w3 + w6;       // west col, interior row
        g_colw[1][co] = w3 + w6;            // west col, top row (tap0 already in rowc)
        g_colw[2][co] = w0 + w3;            // west col, bottom row
        g_cole[0][co] = w2 + w5 + w8;
        g_cole[1][co] = w5 + w8;
        g_cole[2][co] = w2 + w5;
    }
}

// ---------------- K1: sliding-window popcount conv + fused exact BN stats ------
// 16x16 pixel tile per block. 256 threads = 32 channel-pairs x 8 pixel-groups
// (each group owns 2 rows of 16 pixels, walked with a 3x3 u64 window).
__global__ __launch_bounds__(256, 2) void conv_k() {
    __shared__ u64 xs[18*18];
    __shared__ int sRow[3][Cc], sW[3][Cc], sE[3][Cc];
    __shared__ int st[4][8][32];

    int tid  = threadIdx.x;
    int pair = tid & 31;
    int grp  = tid >> 5;
    int n  = blockIdx.z;
    int h0 = blockIdx.y * 16, w0 = blockIdx.x * 16;

    // halo'd x-bits tile (zero-fill outside image)
    for (int j = tid; j < 18*18; j += 256) {
        int lh = j / 18, lw = j - lh*18;
        int gh = h0 + lh - 1, gw = w0 + lw - 1;
        u64 v = 0ull;
        if (gh >= 0 && gh < Hh && gw >= 0 && gw < Wd)
            v = g_xbits[(size_t)n*HW + gh*Wd + gw];
        xs[j] = v;
    }
    if (tid < 192) {
        int r = tid >> 6, c = tid & 63;
        sRow[r][c] = g_rowc[r][c];
        sW[r][c]   = g_colw[r][c];
        sE[r][c]   = g_cole[r][c];
    }

    int c0 = pair*2;
    u64 wb0[9], wb1[9];
    #pragma unroll
    for (int t = 0; t < 9; t++) {
        wb0[t] = g_wbits[c0*9 + t];
        wb1[t] = g_wbits[(c0+1)*9 + t];
    }
    __syncthreads();

    const bool wleft  = (w0 == 0);
    const bool wright = (w0 == Wd-16);
    int as0 = 0, ass0 = 0, as1 = 0, ass1 = 0;

    #pragma unroll
    for (int r = 0; r < 2; r++) {
        int ohl = grp*2 + r;
        int oh  = h0 + ohl;
        int rp  = (oh == 0) ? 1 : ((oh == Hh-1) ? 2 : 0);
        int base0 = 576 - sRow[rp][c0];
        int base1 = 576 - sRow[rp][c0+1];
        int cw0 = sW[rp][c0], cw1 = sW[rp][c0+1];
        int ce0 = sE[rp][c0], ce1 = sE[rp][c0+1];

        const u64* r0p = &xs[ohl*18];
        const u64* r1p = r0p + 18;
        const u64* r2p = r1p + 18;
        u64 x00 = r0p[0], x01 = r0p[1];
        u64 x10 = r1p[0], x11 = r1p[1];
        u64 x20 = r2p[0], x21 = r2p[1];

        unsigned* orow = ((unsigned*)g_conv) + ((size_t)n*HW + (size_t)oh*Wd + w0)*32 + pair;

        #pragma unroll
        for (int w = 0; w < 16; w++) {
            u64 x02 = r0p[w+2], x12 = r1p[w+2], x22 = r2p[w+2];
            int pc0 = __popcll(x00^wb0[0]) + __popcll(x01^wb0[1]) + __popcll(x02^wb0[2])
                    + __popcll(x10^wb0[3]) + __popcll(x11^wb0[4]) + __popcll(x12^wb0[5])
                    + __popcll(x20^wb0[6]) + __popcll(x21^wb0[7]) + __popcll(x22^wb0[8]);
            int pc1 = __popcll(x00^wb1[0]) + __popcll(x01^wb1[1]) + __popcll(x02^wb1[2])
                    + __popcll(x10^wb1[3]) + __popcll(x11^wb1[4]) + __popcll(x12^wb1[5])
                    + __popcll(x20^wb1[6]) + __popcll(x21^wb1[7]) + __popcll(x22^wb1[8]);
            int s0 = base0 - 2*pc0;
            int s1 = base1 - 2*pc1;
            if (w == 0  && wleft)  { s0 -= cw0; s1 -= cw1; }
            if (w == 15 && wright) { s0 -= ce0; s1 -= ce1; }

            as0 += s0; ass0 += s0*s0;
            as1 += s1; ass1 += s1*s1;
            orow[(size_t)w*32] = ((unsigned)s0 & 0xFFFFu) | ((unsigned)s1 << 16);

            x00 = x01; x01 = x02;
            x10 = x11; x11 = x12;
            x20 = x21; x21 = x22;
        }
    }

    st[0][grp][pair] = as0; st[1][grp][pair] = ass0;
    st[2][grp][pair] = as1; st[3][grp][pair] = ass1;
    __syncthreads();
    if (grp == 0) {
        int bs0=0, bss0=0, bs1=0, bss1=0;
        #pragma unroll
        for (int g = 0; g < 8; g++) {
            bs0 += st[0][g][pair]; bss0 += st[1][g][pair];
            bs1 += st[2][g][pair]; bss1 += st[3][g][pair];
        }
        atomicAdd((unsigned long long*)&g_sum[c0],   (unsigned long long)(long long)bs0);
        atomicAdd((unsigned long long*)&g_ss[c0],    (unsigned long long)(long long)bss0);
        atomicAdd((unsigned long long*)&g_sum[c0+1], (unsigned long long)(long long)bs1);
        atomicAdd((unsigned long long*)&g_ss[c0+1],  (unsigned long long)(long long)bss1);
    }
}

// ---------------- K2: per-block affine fold + hardtanh + residual --------------
__global__ __launch_bounds__(256) void apply_k(const float* __restrict__ x,
                                               const float* __restrict__ gamma,
                                               const float* __restrict__ beta,
                                               float* __restrict__ out) {
    __shared__ float sA[Cc], sB[Cc];
    int tid = threadIdx.x;
    if (tid < Cc) {
        int c = tid;
        double mean = (double)g_sum[c] / (double)NHW;
        double ex2  = (double)g_ss[c]  / (double)NHW;
        double a    = (double)g_alpha[c];
        double var  = a*a*(ex2 - mean*mean);
        double rs   = 1.0 / sqrt(var + BN_EPS);
        double g    = (double)gamma[c];
        sA[c] = (float)(a * rs * g);
        sB[c] = (float)((double)beta[c] - a * mean * rs * g);
    }
    __syncthreads();

    size_t P = (size_t)blockIdx.x*256 + tid;      // global pixel id
    int n = (int)(P / HW);
    int p = (int)(P - (size_t)n*HW);
    const uint4* cb = (const uint4*)g_conv + P*8;           // 128B of NHWC shorts
    const float* xb = x   + (size_t)n*Cc*HW + p;
    float*       ob = out + (size_t)n*Cc*HW + p;

    #pragma unroll
    for (int q = 0; q < 8; q++) {
        uint4 v = cb[q];
        #pragma unroll
        for (int w = 0; w < 4; w++) {
            uint32_t u = (&v.x)[w];
            int cA = (q*4 + w)*2;
            int sv0 = (int)((int32_t)(u << 16) >> 16);
            int sv1 = (int)((int32_t)u >> 16);
            float r0 = fminf(fmaxf(fmaf((float)sv0, sA[cA],   sB[cA]),   -1.f), 1.f);
            float r1 = fminf(fmaxf(fmaf((float)sv1, sA[cA+1], sB[cA+1]), -1.f), 1.f);
            ob[(size_t)cA*HW]     = r0 + xb[(size_t)cA*HW];
            ob[(size_t)(cA+1)*HW] = r1 + xb[(size_t)(cA+1)*HW];
        }
    }
}

// ---------------- launcher ------------------------------------------------------
extern "C" void kernel_launch(void* const* d_in, const int* in_sizes, int n_in,
                              void* d_out, int out_size) {
    const float* x     = (const float*)d_in[0];
    const float* W     = (const float*)d_in[1];
    const float* gamma = (const float*)d_in[2];
    const float* beta  = (const float*)d_in[3];
    float* out = (float*)d_out;

    pack_k<<<PACKX_BLOCKS + 1, 256>>>(x, W);
    conv_k<<<dim3(7, 7, Nn), 256>>>();
    apply_k<<<NHW/256, 256>>>(x, gamma, beta, out);
}

// round 5
// speedup vs baseline: 1.2800x; 1.0452x over previous
#include <cuda_runtime.h>
#include <cstdint>

#define Nn 32
#define Cc 64
#define Hh 112
#define Wd 112
#define HW (Hh*Wd)            // 12544
#define NHW (Nn*HW)           // 401408  (= 392 * 1024 exactly)
#define TOT (Nn*Cc*HW)        // 25690112
#define BN_EPS 1e-5
#define PACKX_BLOCKS (NHW/1024)  // 392

typedef unsigned long long u64;

// ---------------- scratch (device globals) -------------------------------------
__device__ u64       g_xbits[NHW];      // packed input signs (3.2 MB)
__device__ u64       g_wbits[Cc*9];     // packed weight signs
__device__ int       g_rowc[3][Cc];     // row-edge corr: [none,N,S]
__device__ int       g_colw[3][Cc];     // west-col corr given row pattern
__device__ int       g_cole[3][Cc];     // east-col corr given row pattern
__device__ float     g_alpha[Cc];
__device__ long long g_sum[Cc];
__device__ long long g_ss[Cc];
__device__ short     g_conv[TOT];       // NHWC [n][p][c] int16 conv result

// ---------------- K0: pack x signs (vectorized) + pack W (last block) ----------
__global__ __launch_bounds__(256) void pack_k(const float* __restrict__ x,
                                              const float* __restrict__ W) {
    int tid = threadIdx.x;
    if (blockIdx.x < PACKX_BLOCKS) {
        // 4 consecutive pixels per thread; float4 loads per channel plane
        int idx = (blockIdx.x*256 + tid) * 4;       // first pixel id
        int n = idx / HW;
        int p = idx - n*HW;                          // HW %4==0 -> all 4 same image
        const float4* base = (const float4*)(x + (size_t)n*Cc*HW + p);
        unsigned lo0=0, lo1=0, lo2=0, lo3=0, hi0=0, hi1=0, hi2=0, hi3=0;
        #pragma unroll
        for (int c = 0; c < 32; c++) {
            float4 v = base[(size_t)c*(HW/4)];
            lo0 |= (__float_as_uint(v.x) >> 31) << c;
            lo1 |= (__float_as_uint(v.y) >> 31) << c;
            lo2 |= (__float_as_uint(v.z) >> 31) << c;
            lo3 |= (__float_as_uint(v.w) >> 31) << c;
        }
        #pragma unroll
        for (int c = 0; c < 32; c++) {
            float4 v = base[(size_t)(c+32)*(HW/4)];
            hi0 |= (__float_as_uint(v.x) >> 31) << c;
            hi1 |= (__float_as_uint(v.y) >> 31) << c;
            hi2 |= (__float_as_uint(v.z) >> 31) << c;
            hi3 |= (__float_as_uint(v.w) >> 31) << c;
        }
        ulonglong2* dst = (ulonglong2*)&g_xbits[idx];
        dst[0] = make_ulonglong2(((u64)hi0 << 32) | lo0, ((u64)hi1 << 32) | lo1);
        dst[1] = make_ulonglong2(((u64)hi2 << 32) | lo2, ((u64)hi3 << 32) | lo3);
        return;
    }
    // ---- weight packing block ----
    __shared__ float asum[576];
    __shared__ int   wd_s[Cc][9];
    for (int i = tid; i < 576; i += 256) {
        int co = i / 9, tap = i - co*9;
        u64 bits = 0ull;
        float a = 0.f;
        for (int ci = 0; ci < Cc; ci++) {
            float w = W[(size_t)(co*Cc + ci)*9 + tap];
            a += fabsf(w);
            bits |= ((u64)(__float_as_uint(w) >> 31)) << ci;
        }
        g_wbits[i]    = bits;
        wd_s[co][tap] = 64 - 2*__popcll(bits);
        asum[i]       = a;
    }
    if (tid < Cc) { g_sum[tid] = 0; g_ss[tid] = 0; }
    __syncthreads();
    if (tid < Cc) {
        int co = tid;
        float t = 0.f;
        #pragma unroll
        for (int k = 0; k < 9; k++) t += asum[co*9 + k];
        g_alpha[co] = t / 576.f;
        int w0=wd_s[co][0], w1=wd_s[co][1], w2=wd_s[co][2];
        int w3=wd_s[co][3],               w5=wd_s[co][5];
        int w6=wd_s[co][6], w7=wd_s[co][7], w8=wd_s[co][8];
        g_rowc[0][co] = 0;
        g_rowc[1][co] = w0 + w1 + w2;
        g_rowc[2][co] = w6 + w7 + w8;
        g_colw[0][co] = w0 + w3 + w6;
        g_colw[1][co] = w3 + w6;
        g_colw[2][co] = w0 + w3;
        g_cole[0][co] = w2 + w5 + w8;
        g_cole[1][co] = w5 + w8;
        g_cole[2][co] = w2 + w5;
    }
}

// ---------------- K1: sliding-window popcount conv + fused exact BN stats ------
__global__ __launch_bounds__(256, 2) void conv_k() {
    __shared__ u64 xs[18*18];
    __shared__ int sRow[3][Cc], sW[3][Cc], sE[3][Cc];
    __shared__ int st[4][8][32];

    int tid  = threadIdx.x;
    int pair = tid & 31;
    int grp  = tid >> 5;
    int n  = blockIdx.z;
    int h0 = blockIdx.y * 16, w0 = blockIdx.x * 16;

    for (int j = tid; j < 18*18; j += 256) {
        int lh = j / 18, lw = j - lh*18;
        int gh = h0 + lh - 1, gw = w0 + lw - 1;
        u64 v = 0ull;
        if (gh >= 0 && gh < Hh && gw >= 0 && gw < Wd)
            v = g_xbits[(size_t)n*HW + gh*Wd + gw];
        xs[j] = v;
    }
    if (tid < 192) {
        int r = tid >> 6, c = tid & 63;
        sRow[r][c] = g_rowc[r][c];
        sW[r][c]   = g_colw[r][c];
        sE[r][c]   = g_cole[r][c];
    }

    int c0 = pair*2;
    u64 wb0[9], wb1[9];
    #pragma unroll
    for (int t = 0; t < 9; t++) {
        wb0[t] = g_wbits[c0*9 + t];
        wb1[t] = g_wbits[(c0+1)*9 + t];
    }
    __syncthreads();

    const bool wleft  = (w0 == 0);
    const bool wright = (w0 == Wd-16);
    int as0 = 0, ass0 = 0, as1 = 0, ass1 = 0;

    #pragma unroll
    for (int r = 0; r < 2; r++) {
        int ohl = grp*2 + r;
        int oh  = h0 + ohl;
        int rp  = (oh == 0) ? 1 : ((oh == Hh-1) ? 2 : 0);
        int base0 = 576 - sRow[rp][c0];
        int base1 = 576 - sRow[rp][c0+1];
        int cw0 = sW[rp][c0], cw1 = sW[rp][c0+1];
        int ce0 = sE[rp][c0], ce1 = sE[rp][c0+1];

        const u64* r0p = &xs[ohl*18];
        const u64* r1p = r0p + 18;
        const u64* r2p = r1p + 18;
        u64 x00 = r0p[0], x01 = r0p[1];
        u64 x10 = r1p[0], x11 = r1p[1];
        u64 x20 = r2p[0], x21 = r2p[1];

        unsigned* op = ((unsigned*)g_conv) + ((size_t)n*HW + (size_t)oh*Wd + w0)*32 + pair;

        #pragma unroll
        for (int w = 0; w < 16; w++) {
            u64 x02 = r0p[w+2], x12 = r1p[w+2], x22 = r2p[w+2];
            int pc0 = __popcll(x00^wb0[0]) + __popcll(x01^wb0[1]) + __popcll(x02^wb0[2])
                    + __popcll(x10^wb0[3]) + __popcll(x11^wb0[4]) + __popcll(x12^wb0[5])
                    + __popcll(x20^wb0[6]) + __popcll(x21^wb0[7]) + __popcll(x22^wb0[8]);
            int pc1 = __popcll(x00^wb1[0]) + __popcll(x01^wb1[1]) + __popcll(x02^wb1[2])
                    + __popcll(x10^wb1[3]) + __popcll(x11^wb1[4]) + __popcll(x12^wb1[5])
                    + __popcll(x20^wb1[6]) + __popcll(x21^wb1[7]) + __popcll(x22^wb1[8]);
            int s0 = base0 - 2*pc0;
            int s1 = base1 - 2*pc1;
            if (w == 0  && wleft)  { s0 -= cw0; s1 -= cw1; }
            if (w == 15 && wright) { s0 -= ce0; s1 -= ce1; }

            as0 += s0; ass0 += s0*s0;
            as1 += s1; ass1 += s1*s1;
            *op = ((unsigned)s0 & 0xFFFFu) | ((unsigned)s1 << 16);
            op += 32;

            x00 = x01; x01 = x02;
            x10 = x11; x11 = x12;
            x20 = x21; x21 = x22;
        }
    }

    st[0][grp][pair] = as0; st[1][grp][pair] = ass0;
    st[2][grp][pair] = as1; st[3][grp][pair] = ass1;
    __syncthreads();
    if (grp == 0) {
        int bs0=0, bss0=0, bs1=0, bss1=0;
        #pragma unroll
        for (int g = 0; g < 8; g++) {
            bs0 += st[0][g][pair]; bss0 += st[1][g][pair];
            bs1 += st[2][g][pair]; bss1 += st[3][g][pair];
        }
        atomicAdd((unsigned long long*)&g_sum[c0],   (unsigned long long)(long long)bs0);
        atomicAdd((unsigned long long*)&g_ss[c0],    (unsigned long long)(long long)bss0);
        atomicAdd((unsigned long long*)&g_sum[c0+1], (unsigned long long)(long long)bs1);
        atomicAdd((unsigned long long*)&g_ss[c0+1],  (unsigned long long)(long long)bss1);
    }
}

// ---------------- K2: per-block affine fold + hardtanh + residual --------------
__global__ __launch_bounds__(256) void apply_k(const float* __restrict__ x,
                                               const float* __restrict__ gamma,
                                               const float* __restrict__ beta,
                                               float* __restrict__ out) {
    __shared__ float sA[Cc], sB[Cc];
    int tid = threadIdx.x;
    if (tid < Cc) {
        int c = tid;
        double mean = (double)g_sum[c] / (double)NHW;
        double ex2  = (double)g_ss[c]  / (double)NHW;
        double a    = (double)g_alpha[c];
        double var  = a*a*(ex2 - mean*mean);
        double rs   = 1.0 / sqrt(var + BN_EPS);
        double g    = (double)gamma[c];
        sA[c] = (float)(a * rs * g);
        sB[c] = (float)((double)beta[c] - a * mean * rs * g);
    }
    __syncthreads();

    size_t P = (size_t)blockIdx.x*256 + tid;      // global pixel id
    int n = (int)(P / HW);
    int p = (int)(P - (size_t)n*HW);
    const uint4* cb = (const uint4*)g_conv + P*8;           // 128B of NHWC shorts
    const float* xb = x   + (size_t)n*Cc*HW + p;
    float*       ob = out + (size_t)n*Cc*HW + p;

    #pragma unroll
    for (int q = 0; q < 8; q++) {
        uint4 v = cb[q];
        #pragma unroll
        for (int w = 0; w < 4; w++) {
            uint32_t u = (&v.x)[w];
            int cA = (q*4 + w)*2;
            int sv0 = (int)((int32_t)(u << 16) >> 16);
            int sv1 = (int)((int32_t)u >> 16);
            float r0 = fminf(fmaxf(fmaf((float)sv0, sA[cA],   sB[cA]),   -1.f), 1.f);
            float r1 = fminf(fmaxf(fmaf((float)sv1, sA[cA+1], sB[cA+1]), -1.f), 1.f);
            ob[(size_t)cA*HW]     = r0 + xb[(size_t)cA*HW];
            ob[(size_t)(cA+1)*HW] = r1 + xb[(size_t)(cA+1)*HW];
        }
    }
}

// ---------------- launcher ------------------------------------------------------
extern "C" void kernel_launch(void* const* d_in, const int* in_sizes, int n_in,
                              void* d_out, int out_size) {
    const float* x     = (const float*)d_in[0];
    const float* W     = (const float*)d_in[1];
    const float* gamma = (const float*)d_in[2];
    const float* beta  = (const float*)d_in[3];
    float* out = (float*)d_out;

    pack_k<<<PACKX_BLOCKS + 1, 256>>>(x, W);
    conv_k<<<dim3(7, 7, Nn), 256>>>();
    apply_k<<<NHW/256, 256>>>(x, gamma, beta, out);
}